// round 1
// baseline (speedup 1.0000x reference)
#include <cuda_runtime.h>
#include <cuda_bf16.h>
#include <cstdint>

// Problem constants
#define N_STREAMS 8
#define D_MODEL   2048
#define NS        16           // N_STREAMS * S_EXP
#define N_SKEW    120          // NS*(NS-1)/2
#define KPAD      128          // padded skew outputs
#define TOKENS    8192         // B*L = 2*4096
#define TPC       16           // tokens per CTA
#define THREADS   512
#define NTILES    (TOKENS / TPC)   // 512
#define DP_TOTAL  (D_MODEL / 2)    // 1024 d-pairs

// Scratch: W transposed + f32x2-packed:  Wt2[dp][k] = (W[k][2dp], W[k][2dp+1]); zero for k>=120
__device__ float2 g_Wt2[DP_TOTAL * KPAD];   // 1 MB static

__global__ void prep_wt_kernel(const float* __restrict__ W) {
    int id = blockIdx.x * blockDim.x + threadIdx.x;   // 131072 total
    int dp = id & (DP_TOTAL - 1);
    int k  = id >> 10;
    float2 v = make_float2(0.f, 0.f);
    if (k < N_SKEW) {
        v.x = W[k * D_MODEL + 2 * dp];
        v.y = W[k * D_MODEL + 2 * dp + 1];
    }
    g_Wt2[dp * KPAD + k] = v;
}

__device__ __forceinline__ void fma2(unsigned long long& acc,
                                     unsigned long long a,
                                     unsigned long long b) {
    asm("fma.rn.f32x2 %0, %1, %2, %0;" : "+l"(acc) : "l"(a), "l"(b));
}

// Dynamic smem layout: xs[TPC][D_MODEL] floats, then zs[TPC][KPAD] floats
#define SMEM_FLOATS (TPC * D_MODEL + TPC * KPAD)
#define SMEM_BYTES  (SMEM_FLOATS * 4)

extern "C" __global__ void __launch_bounds__(THREADS, 1)
gomhc_fused_kernel(const float* __restrict__ streams,
                   const float* __restrict__ bias,
                   float* __restrict__ out) {
    extern __shared__ float smem[];
    float* xs = smem;                       // [16][2048]
    float* zs = smem + TPC * D_MODEL;       // [16][128]

    const int tid  = threadIdx.x;
    const int tile = blockIdx.x;

    // ---- zero z accumulators ----
    for (int i = tid; i < TPC * KPAD; i += THREADS) zs[i] = 0.f;

    // ---- Phase A: load streams + mean over n into shared ----
    // per token: 8 * 2048 floats = 4096 float4 (n-stride = 512 float4)
    {
        const float4* s4 = reinterpret_cast<const float4*>(streams)
                         + (size_t)tile * TPC * (N_STREAMS * D_MODEL / 4);
        float4* xs4 = reinterpret_cast<float4*>(xs);
        #pragma unroll 1
        for (int t = 0; t < TPC; t++) {
            const float4* tb = s4 + t * (N_STREAMS * D_MODEL / 4);
            float4 a = tb[tid];
            #pragma unroll
            for (int n = 1; n < N_STREAMS; n++) {
                float4 v = tb[tid + n * (D_MODEL / 4)];
                a.x += v.x; a.y += v.y; a.z += v.z; a.w += v.w;
            }
            a.x *= 0.125f; a.y *= 0.125f; a.z *= 0.125f; a.w *= 0.125f;
            xs4[t * (D_MODEL / 4) + tid] = a;
        }
    }
    __syncthreads();

    // ---- Phase B: GEMV  z[t][k] = sum_d W[k][d] * xs[t][d]  (f32x2 packed) ----
    {
        const int kg = tid & 31;          // 32 k-groups (4 k each -> 128 k)
        const int tg = (tid >> 5) & 1;    // 2 token-groups of 8
        const int ds = tid >> 6;          // 8-way d split (128 dp each)

        const ulonglong2* Wp = reinterpret_cast<const ulonglong2*>(g_Wt2);
        const float* xbase = xs + (tg * 8) * D_MODEL;

        unsigned long long acc[4][8];
        #pragma unroll
        for (int i = 0; i < 4; i++)
            #pragma unroll
            for (int t = 0; t < 8; t++) acc[i][t] = 0ull;

        const int dp0 = ds * (DP_TOTAL / 8);
        #pragma unroll 2
        for (int dp = dp0; dp < dp0 + (DP_TOTAL / 8); dp++) {
            // Wt2 row: 128 float2 = 64 ulonglong2; lane kg takes k = 4kg..4kg+3
            ulonglong2 wa = Wp[dp * 64 + 2 * kg];       // k=4kg, 4kg+1
            ulonglong2 wb = Wp[dp * 64 + 2 * kg + 1];   // k=4kg+2, 4kg+3
            #pragma unroll
            for (int t = 0; t < 8; t++) {
                unsigned long long x2 =
                    *reinterpret_cast<const unsigned long long*>(xbase + t * D_MODEL + 2 * dp);
                fma2(acc[0][t], wa.x, x2);
                fma2(acc[1][t], wa.y, x2);
                fma2(acc[2][t], wb.x, x2);
                fma2(acc[3][t], wb.y, x2);
            }
        }

        #pragma unroll
        for (int i = 0; i < 4; i++) {
            #pragma unroll
            for (int t = 0; t < 8; t++) {
                float2 v = *reinterpret_cast<float2*>(&acc[i][t]);
                atomicAdd(&zs[(tg * 8 + t) * KPAD + 4 * kg + i], v.x + v.y);
            }
        }
    }
    __syncthreads();

    // ---- bias add ----
    for (int i = tid; i < TPC * N_SKEW; i += THREADS) {
        int t = i / N_SKEW, k = i - t * N_SKEW;
        zs[t * KPAD + k] += bias[k];
    }
    __syncthreads();

    // ---- Phase C: Cayley solve + block Frobenius, one warp per token ----
    {
        const int warp = tid >> 5;         // 0..15 -> token
        const int lane = tid & 31;
        const int r    = lane & 15;        // row owned (lanes 16-31 duplicate)
        const float* zt = zs + warp * KPAD;

        // Build augmented [ I+A | I-A ] row r
        float m[32];
        #pragma unroll
        for (int c = 0; c < NS; c++) {
            float a = 0.f;
            if (c > r)      a =  zt[(r * (31 - r)) / 2 + (c - r - 1)];
            else if (c < r) a = -zt[(c * (31 - c)) / 2 + (r - c - 1)];
            float diag = (c == r) ? 1.f : 0.f;
            m[c]      = diag + a;
            m[16 + c] = diag - a;
        }

        // Gauss-Jordan (no pivoting; I+A has SPD symmetric part)
        const unsigned mask = 0xffffffffu;
        #pragma unroll
        for (int i = 0; i < NS; i++) {
            float piv[32];
            #pragma unroll
            for (int k = 0; k < 32; k++) piv[k] = __shfl_sync(mask, m[k], i);
            float rp = 1.0f / piv[i];
            if (r == i) {
                #pragma unroll
                for (int k = 0; k < 32; k++) m[k] *= rp;
            } else {
                float f = m[i] * rp;
                #pragma unroll
                for (int k = 0; k < 32; k++) m[k] = fmaf(-f, piv[k], m[k]);
            }
        }

        // Q row r = m[16..31].  H[p][q] = 0.5 * sum_{a,b} Q[2p+a][2q+b]^2
        float hq[8];
        #pragma unroll
        for (int q = 0; q < 8; q++) {
            float q0 = m[16 + 2 * q], q1 = m[16 + 2 * q + 1];
            hq[q] = q0 * q0 + q1 * q1;
        }
        #pragma unroll
        for (int q = 0; q < 8; q++)
            hq[q] += __shfl_xor_sync(mask, hq[q], 1);

        if (lane < 16 && !(r & 1)) {
            const int tok = tile * TPC + warp;
            float* o = out + (size_t)tok * 64 + (r >> 1) * 8;
            #pragma unroll
            for (int q = 0; q < 8; q++) o[q] = 0.5f * hq[q];
        }
    }
}

extern "C" void kernel_launch(void* const* d_in, const int* in_sizes, int n_in,
                              void* d_out, int out_size) {
    const float* streams = (const float*)d_in[0];
    const float* W       = (const float*)d_in[1];
    const float* b       = (const float*)d_in[2];
    float* out = (float*)d_out;

    // Re-pack W every launch (deterministic, graph-capturable, tiny: 1 MB)
    prep_wt_kernel<<<(DP_TOTAL * KPAD) / 256, 256>>>(W);

    cudaFuncSetAttribute(gomhc_fused_kernel,
                         cudaFuncAttributeMaxDynamicSharedMemorySize, SMEM_BYTES);
    gomhc_fused_kernel<<<NTILES, THREADS, SMEM_BYTES>>>(streams, b, out);
}

// round 2
// speedup vs baseline: 1.0167x; 1.0167x over previous
#include <cuda_runtime.h>
#include <cuda_bf16.h>
#include <cstdint>

// Problem constants
#define N_STREAMS 8
#define D_MODEL   2048
#define NS        16           // N_STREAMS * S_EXP
#define N_SKEW    120          // NS*(NS-1)/2
#define KPAD      128          // padded skew outputs
#define TOKENS    8192         // B*L = 2*4096
#define TPC       16           // tokens per CTA
#define THREADS   512
#define NTILES    (TOKENS / TPC)   // 512
#define DP_TOTAL  (D_MODEL / 2)    // 1024 d-pairs

// W transposed + f32x2-packed: g_Wt2[dp*KPAD + k] = (W[k][2dp], W[k][2dp+1]); zero for k>=120
__device__ float2 g_Wt2[DP_TOTAL * KPAD];   // 1 MB static

__global__ void prep_wt_kernel(const float* __restrict__ W) {
    int id = blockIdx.x * blockDim.x + threadIdx.x;   // 131072 total
    int dp = id & (DP_TOTAL - 1);
    int k  = id >> 10;
    float2 v = make_float2(0.f, 0.f);
    if (k < N_SKEW) {
        v.x = W[k * D_MODEL + 2 * dp];
        v.y = W[k * D_MODEL + 2 * dp + 1];
    }
    g_Wt2[dp * KPAD + k] = v;
}

__device__ __forceinline__ void fma2(unsigned long long& acc,
                                     unsigned long long a,
                                     unsigned long long b) {
    asm("fma.rn.f32x2 %0, %1, %2, %0;" : "+l"(acc) : "l"(a), "l"(b));
}

// Dynamic smem: xs[TPC][D_MODEL] floats, then zs[TPC][KPAD] floats
#define SMEM_FLOATS (TPC * D_MODEL + TPC * KPAD)
#define SMEM_BYTES  (SMEM_FLOATS * 4)

extern "C" __global__ void __launch_bounds__(THREADS, 1)
gomhc_fused_kernel(const float* __restrict__ streams,
                   const float* __restrict__ bias,
                   float* __restrict__ out) {
    extern __shared__ float smem[];
    float* xs = smem;                       // [16][2048]
    float* zs = smem + TPC * D_MODEL;       // [16][128]

    const int tid  = threadIdx.x;
    const int tile = blockIdx.x;

    // ---- zero z accumulators ----
    for (int i = tid; i < TPC * KPAD; i += THREADS) zs[i] = 0.f;

    // ---- Phase A: load streams + mean over n -> shared (2 tokens interleaved) ----
    {
        const float4* s4 = reinterpret_cast<const float4*>(streams)
                         + (size_t)tile * TPC * (N_STREAMS * D_MODEL / 4);
        float4* xs4 = reinterpret_cast<float4*>(xs);
        #pragma unroll 1
        for (int t = 0; t < TPC; t += 2) {
            const float4* tb0 = s4 + (t    ) * (N_STREAMS * D_MODEL / 4);
            const float4* tb1 = s4 + (t + 1) * (N_STREAMS * D_MODEL / 4);
            float4 v[N_STREAMS], u[N_STREAMS];
            #pragma unroll
            for (int n = 0; n < N_STREAMS; n++) {
                v[n] = tb0[tid + n * (D_MODEL / 4)];
                u[n] = tb1[tid + n * (D_MODEL / 4)];
            }
            // pairwise reduction trees (shallow dep chains)
            #pragma unroll
            for (int s = N_STREAMS / 2; s > 0; s >>= 1) {
                #pragma unroll
                for (int n = 0; n < s; n++) {
                    v[n].x += v[n+s].x; v[n].y += v[n+s].y;
                    v[n].z += v[n+s].z; v[n].w += v[n+s].w;
                    u[n].x += u[n+s].x; u[n].y += u[n+s].y;
                    u[n].z += u[n+s].z; u[n].w += u[n+s].w;
                }
            }
            v[0].x *= 0.125f; v[0].y *= 0.125f; v[0].z *= 0.125f; v[0].w *= 0.125f;
            u[0].x *= 0.125f; u[0].y *= 0.125f; u[0].z *= 0.125f; u[0].w *= 0.125f;
            xs4[(t    ) * (D_MODEL / 4) + tid] = v[0];
            xs4[(t + 1) * (D_MODEL / 4) + tid] = u[0];
        }
    }
    __syncthreads();

    // ---- Phase B: GEMV  z[t][k] = sum_d W[k][d]*xs[t][d] ----
    // Tiling: kg = tid&63 -> k = {2kg, 2kg+1};  ds = tid>>6 -> 8-way d split (128 dp each).
    // All 16 tokens per thread => full W streamed exactly ONCE per CTA.
    {
        const int kg = tid & 63;
        const int ds = tid >> 6;

        const ulonglong2* __restrict__ Wp = reinterpret_cast<const ulonglong2*>(g_Wt2);

        unsigned long long acc0[TPC], acc1[TPC];
        #pragma unroll
        for (int t = 0; t < TPC; t++) { acc0[t] = 0ull; acc1[t] = 0ull; }

        const int dp0 = ds * (DP_TOTAL / 8);
        #pragma unroll 4
        for (int dp = dp0; dp < dp0 + (DP_TOTAL / 8); dp++) {
            // one ulonglong2 = W pairs for k=2kg (x) and k=2kg+1 (y) at this dp
            ulonglong2 w = Wp[dp * (KPAD / 2) + kg];
            const float* xrow = xs + 2 * dp;
            #pragma unroll
            for (int t = 0; t < TPC; t++) {
                unsigned long long x2 =
                    *reinterpret_cast<const unsigned long long*>(xrow + t * D_MODEL);
                fma2(acc0[t], w.x, x2);
                fma2(acc1[t], w.y, x2);
            }
        }

        #pragma unroll
        for (int t = 0; t < TPC; t++) {
            float2 a = *reinterpret_cast<float2*>(&acc0[t]);
            float2 b = *reinterpret_cast<float2*>(&acc1[t]);
            atomicAdd(&zs[t * KPAD + 2 * kg    ], a.x + a.y);
            atomicAdd(&zs[t * KPAD + 2 * kg + 1], b.x + b.y);
        }
    }
    __syncthreads();

    // ---- bias add ----
    for (int i = tid; i < TPC * N_SKEW; i += THREADS) {
        int t = i / N_SKEW, k = i - t * N_SKEW;
        zs[t * KPAD + k] += bias[k];
    }
    __syncthreads();

    // ---- Phase C: Cayley solve + block Frobenius, one warp per token ----
    {
        const int warp = tid >> 5;         // token within tile
        const int lane = tid & 31;
        const int r    = lane & 15;        // row owned (lanes 16-31 duplicate)
        const float* zt = zs + warp * KPAD;

        // Build augmented [ I+A | I-A ] row r
        float m[32];
        #pragma unroll
        for (int c = 0; c < NS; c++) {
            float a = 0.f;
            if (c > r)      a =  zt[(r * (31 - r)) / 2 + (c - r - 1)];
            else if (c < r) a = -zt[(c * (31 - c)) / 2 + (r - c - 1)];
            float diag = (c == r) ? 1.f : 0.f;
            m[c]      = diag + a;
            m[16 + c] = diag - a;
        }

        // Gauss-Jordan (no pivoting; I+A has SPD symmetric part)
        const unsigned mask = 0xffffffffu;
        #pragma unroll
        for (int i = 0; i < NS; i++) {
            float piv[32];
            #pragma unroll
            for (int k = 0; k < 32; k++) piv[k] = __shfl_sync(mask, m[k], i);
            float rp = 1.0f / piv[i];
            if (r == i) {
                #pragma unroll
                for (int k = 0; k < 32; k++) m[k] *= rp;
            } else {
                float f = m[i] * rp;
                #pragma unroll
                for (int k = 0; k < 32; k++) m[k] = fmaf(-f, piv[k], m[k]);
            }
        }

        // Q row r = m[16..31].  H[p][q] = 0.5 * sum over 2x2 block of Q^2
        float hq[8];
        #pragma unroll
        for (int q = 0; q < 8; q++) {
            float q0 = m[16 + 2 * q], q1 = m[16 + 2 * q + 1];
            hq[q] = q0 * q0 + q1 * q1;
        }
        #pragma unroll
        for (int q = 0; q < 8; q++)
            hq[q] += __shfl_xor_sync(mask, hq[q], 1);

        if (lane < 16 && !(r & 1)) {
            const int tok = tile * TPC + warp;
            float* o = out + (size_t)tok * 64 + (r >> 1) * 8;
            #pragma unroll
            for (int q = 0; q < 8; q++) o[q] = 0.5f * hq[q];
        }
    }
}

extern "C" void kernel_launch(void* const* d_in, const int* in_sizes, int n_in,
                              void* d_out, int out_size) {
    const float* streams = (const float*)d_in[0];
    const float* W       = (const float*)d_in[1];
    const float* b       = (const float*)d_in[2];
    float* out = (float*)d_out;

    prep_wt_kernel<<<(DP_TOTAL * KPAD) / 256, 256>>>(W);

    cudaFuncSetAttribute(gomhc_fused_kernel,
                         cudaFuncAttributeMaxDynamicSharedMemorySize, SMEM_BYTES);
    gomhc_fused_kernel<<<NTILES, THREADS, SMEM_BYTES>>>(streams, b, out);
}